// round 1
// baseline (speedup 1.0000x reference)
#include <cuda_runtime.h>
#include <math.h>

#define BATCH 16
#define N1D 1024
#define CCH 256

// Scratch (device globals; no allocation allowed)
__device__ float g_p1[BATCH * N1D * CCH];      // 16.8 MB : p1 = x1
__device__ float g_x2[BATCH * 256 * CCH];      // 4.2 MB
__device__ float g_x3[BATCH * 64 * CCH];       // 1.05 MB
__device__ float g_att2[BATCH * 256 * 256];    // 4.2 MB
__device__ float g_att3[BATCH * 64 * 64];      // 0.26 MB

// ---------------------------------------------------------------------------
// Projection: out[M,256] = A[M,KDIM] @ W[KDIM,256] + bias   (NN GEMM)
// 64x64 tile, 256 threads, kb=32
// ---------------------------------------------------------------------------
__global__ __launch_bounds__(256) void proj_kernel(
    const float* __restrict__ A, const float* __restrict__ W,
    const float* __restrict__ bias, float* __restrict__ out, int KDIM)
{
    __shared__ float As[32][65];   // [k][row] transposed, padded
    __shared__ float Ws[32][64];   // [k][n]
    const int t  = threadIdx.x;
    const int ty = t >> 4, tx = t & 15;
    const int r0 = ty * 4, c0 = tx * 4;
    const int row0 = blockIdx.x * 64;
    const int n0   = blockIdx.y * 64;

    float acc[4][4] = {};

    for (int k0 = 0; k0 < KDIM; k0 += 32) {
#pragma unroll
        for (int i = 0; i < 8; i++) {
            int lin = t + 256 * i;           // 2048 = 64 rows x 32 k
            int r = lin >> 5, k = lin & 31;
            As[k][r] = A[(size_t)(row0 + r) * KDIM + k0 + k];
        }
#pragma unroll
        for (int i = 0; i < 8; i++) {
            int lin = t + 256 * i;
            int n = lin & 63, k = lin >> 6;
            Ws[k][n] = W[(size_t)(k0 + k) * CCH + n0 + n];
        }
        __syncthreads();
#pragma unroll
        for (int k = 0; k < 32; k++) {
            float a[4];
#pragma unroll
            for (int i = 0; i < 4; i++) a[i] = As[k][r0 + i];
            float4 w4 = *(const float4*)&Ws[k][c0];
#pragma unroll
            for (int i = 0; i < 4; i++) {
                acc[i][0] += a[i] * w4.x;
                acc[i][1] += a[i] * w4.y;
                acc[i][2] += a[i] * w4.z;
                acc[i][3] += a[i] * w4.w;
            }
        }
        __syncthreads();
    }

    float4 bv = *(const float4*)&bias[n0 + c0];
#pragma unroll
    for (int i = 0; i < 4; i++) {
        float4 o;
        o.x = acc[i][0] + bv.x;
        o.y = acc[i][1] + bv.y;
        o.z = acc[i][2] + bv.z;
        o.w = acc[i][3] + bv.w;
        *(float4*)&out[(size_t)(row0 + r0 + i) * CCH + n0 + c0] = o;
    }
}

// ---------------------------------------------------------------------------
// Batched Gram: out[b] = X[b] @ X[b]^T, X:[N,256]   (NT GEMM) 64x64 tiles
// ---------------------------------------------------------------------------
__global__ __launch_bounds__(256) void attnt_kernel(
    const float* __restrict__ X, float* __restrict__ out, int N)
{
    __shared__ float Ai[32][65];
    __shared__ float Bj[32][65];
    const int b  = blockIdx.z;
    const int i0 = blockIdx.x * 64, j0 = blockIdx.y * 64;
    const int t  = threadIdx.x;
    const int ty = t >> 4, tx = t & 15;
    const int r0 = ty * 4, c0 = tx * 4;
    const float* Xb = X + (size_t)b * N * CCH;

    float acc[4][4] = {};

    for (int k0 = 0; k0 < CCH; k0 += 32) {
#pragma unroll
        for (int i = 0; i < 8; i++) {
            int lin = t + 256 * i;
            int r = lin >> 5, k = lin & 31;
            Ai[k][r] = Xb[(size_t)(i0 + r) * CCH + k0 + k];
            Bj[k][r] = Xb[(size_t)(j0 + r) * CCH + k0 + k];
        }
        __syncthreads();
#pragma unroll
        for (int k = 0; k < 32; k++) {
            float a[4], bb[4];
#pragma unroll
            for (int i = 0; i < 4; i++) a[i]  = Ai[k][r0 + i];
#pragma unroll
            for (int j = 0; j < 4; j++) bb[j] = Bj[k][c0 + j];
#pragma unroll
            for (int i = 0; i < 4; i++)
#pragma unroll
                for (int j = 0; j < 4; j++)
                    acc[i][j] += a[i] * bb[j];
        }
        __syncthreads();
    }

#pragma unroll
    for (int i = 0; i < 4; i++) {
        float4 o;
        o.x = acc[i][0]; o.y = acc[i][1]; o.z = acc[i][2]; o.w = acc[i][3];
        *(float4*)&out[(size_t)b * N * N + (size_t)(i0 + r0 + i) * N + j0 + c0] = o;
    }
}

// ---------------------------------------------------------------------------
// Fused attention kernel (flash-style, sigmoid gating, exact legacy-bilinear
// lerp of att2/att3 from their small Gram matrices).
// grid: (16 n-tiles, 16 batches), 256 threads, 1 CTA/SM.
// SMEM tiles are XOR-swizzled at float4-chunk granularity: element [row][ch]
// lives at row*256 + ((ch>>2) ^ ((row>>2)&7))*4 + (ch&3).
// ---------------------------------------------------------------------------
__global__ __launch_bounds__(256, 1) void fused_kernel(
    const float* __restrict__ p1,
    const float* __restrict__ att2, const float* __restrict__ att3,
    const float* __restrict__ pa1, const float* __restrict__ pa2,
    const float* __restrict__ pa3, float* __restrict__ out)
{
    extern __shared__ float sm[];
    float* Qs = sm;                 // 64 x 256 (swizzled)
    float* Ks = Qs + 64 * 256;      // 64 x 256 (swizzled)
    float* Ss = Ks + 64 * 256;      // 64 x 65
    float* A2 = Ss + 64 * 65;       // 17 x 256
    float* A3 = A2 + 17 * 256;      // 5 x 64

    const int b  = blockIdx.y;
    const int n0 = blockIdx.x * 64;
    const int t  = threadIdx.x;
    const int ty = t >> 4, tx = t & 15;
    const int r0 = ty * 4, c0 = tx * 4;
    const int swq = ty & 7;         // Q-row swizzle const for this thread
    const int swk = tx & 7;         // K-row swizzle const (GEMM1)

    const float* p1b = p1 + (size_t)b * N1D * CCH;
    const float sa1 = *pa1, sa2 = *pa2, sa3 = *pa3;
    const int r2lo = n0 >> 2;       // att2 row window base
    const int r3lo = n0 >> 4;       // att3 row window base

    // ---- stage Q tile (this n-tile's x1 rows), swizzled ----
#pragma unroll
    for (int i = 0; i < 16; i++) {
        int lin = t + 256 * i;              // 4096 float4 chunks
        int row = lin >> 6, ck = lin & 63;
        float4 v = *(const float4*)(p1b + (size_t)(n0 + row) * CCH + ck * 4);
        *(float4*)(Qs + row * 256 + ((ck ^ ((row >> 2) & 7)) << 2)) = v;
    }
    // ---- stage att2 row window: 17 rows x 256 cols ----
    for (int lin = t; lin < 17 * 256; lin += 256) {
        int rr = lin >> 8, cc = lin & 255;
        int src_r = min(r2lo + rr, 255);
        A2[rr * 256 + cc] = att2[((size_t)b * 256 + src_r) * 256 + cc];
    }
    // ---- stage att3 row window: 5 rows x 64 cols ----
    for (int lin = t; lin < 5 * 64; lin += 256) {
        int rr = lin >> 6, cc = lin & 63;
        int src_r = min(r3lo + rr, 63);
        A3[rr * 64 + cc] = att3[((size_t)b * 64 + src_r) * 64 + cc];
    }

    float4 Ob[4][4];
#pragma unroll
    for (int i = 0; i < 4; i++)
#pragma unroll
        for (int q = 0; q < 4; q++) Ob[i][q] = make_float4(0.f, 0.f, 0.f, 0.f);

    for (int mt = 0; mt < 16; mt++) {
        const int m0 = mt * 64;
        __syncthreads();   // previous GEMM2 finished reading Ks / A-stages done
        // ---- stage K tile (m-tile's x1 rows), swizzled ----
#pragma unroll
        for (int i = 0; i < 16; i++) {
            int lin = t + 256 * i;
            int row = lin >> 6, ck = lin & 63;
            float4 v = *(const float4*)(p1b + (size_t)(m0 + row) * CCH + ck * 4);
            *(float4*)(Ks + row * 256 + ((ck ^ ((row >> 2) & 7)) << 2)) = v;
        }
        __syncthreads();

        // ---- GEMM1: S[64x64] = Q . K^T over 256 channels ----
        float acc[4][4] = {};
#pragma unroll 4
        for (int ck = 0; ck < 64; ck++) {
            float4 qv[4], kv[4];
#pragma unroll
            for (int i = 0; i < 4; i++)
                qv[i] = *(const float4*)(Qs + (r0 + i) * 256 + ((ck ^ swq) << 2));
#pragma unroll
            for (int j = 0; j < 4; j++)
                kv[j] = *(const float4*)(Ks + (c0 + j) * 256 + ((ck ^ swk) << 2));
#pragma unroll
            for (int i = 0; i < 4; i++)
#pragma unroll
                for (int j = 0; j < 4; j++)
                    acc[i][j] += qv[i].x * kv[j].x + qv[i].y * kv[j].y +
                                 qv[i].z * kv[j].z + qv[i].w * kv[j].w;
        }

        // ---- epilogue: + a2*lerp(att2) + a3*lerp(att3), sigmoid -> Ss ----
#pragma unroll
        for (int i = 0; i < 4; i++) {
            const int n   = n0 + r0 + i;
            const int rn  = n >> 2;
            const float fn  = (float)(n & 3)  * 0.25f;
            const int i20 = rn - r2lo;
            const int i21 = min(rn + 1, 255) - r2lo;
            const int rn3 = n >> 4;
            const float fn3 = (float)(n & 15) * 0.0625f;
            const int i30 = rn3 - r3lo;
            const int i31 = min(rn3 + 1, 63) - r3lo;
#pragma unroll
            for (int j = 0; j < 4; j++) {
                const int m  = m0 + c0 + j;
                const int rm = m >> 2;
                const float fm = (float)(m & 3) * 0.25f;
                const int c21 = min(rm + 1, 255);
                const float* Ar0 = A2 + i20 * 256;
                const float* Ar1 = A2 + i21 * 256;
                float v2 = (1.f - fn) * ((1.f - fm) * Ar0[rm] + fm * Ar0[c21]) +
                           fn        * ((1.f - fm) * Ar1[rm] + fm * Ar1[c21]);

                const int rm3 = m >> 4;
                const float fm3 = (float)(m & 15) * 0.0625f;
                const int c31 = min(rm3 + 1, 63);
                const float* Br0 = A3 + i30 * 64;
                const float* Br1 = A3 + i31 * 64;
                float v3 = (1.f - fn3) * ((1.f - fm3) * Br0[rm3] + fm3 * Br0[c31]) +
                           fn3        * ((1.f - fm3) * Br1[rm3] + fm3 * Br1[c31]);

                float val = sa1 * acc[i][j] + sa2 * v2 + sa3 * v3;
                Ss[(r0 + i) * 65 + (c0 + j)] = 1.0f / (1.0f + expf(-val));
            }
        }
        __syncthreads();

        // ---- GEMM2: O[64x256] += S[64x64] @ K[64x256] ----
#pragma unroll 4
        for (int m = 0; m < 64; m++) {
            float sv[4];
#pragma unroll
            for (int i = 0; i < 4; i++) sv[i] = Ss[(r0 + i) * 65 + m];
            const int swm = (m >> 2) & 7;
#pragma unroll
            for (int q = 0; q < 4; q++) {
                const int chunk = (q << 4) + tx;
                float4 kv = *(const float4*)(Ks + m * 256 + ((chunk ^ swm) << 2));
#pragma unroll
                for (int i = 0; i < 4; i++) {
                    Ob[i][q].x += sv[i] * kv.x;
                    Ob[i][q].y += sv[i] * kv.y;
                    Ob[i][q].z += sv[i] * kv.z;
                    Ob[i][q].w += sv[i] * kv.w;
                }
            }
        }
    }

    // ---- final: out = O + p1  (p1 rows still live in Qs) ----
#pragma unroll
    for (int i = 0; i < 4; i++) {
        const int n = n0 + r0 + i;
        float* orow = out + ((size_t)(b * N1D + n)) * CCH;
#pragma unroll
        for (int q = 0; q < 4; q++) {
            const int chunk = (q << 4) + tx;
            float4 pv = *(const float4*)(Qs + (r0 + i) * 256 + ((chunk ^ swq) << 2));
            float4 o;
            o.x = Ob[i][q].x + pv.x;
            o.y = Ob[i][q].y + pv.y;
            o.z = Ob[i][q].z + pv.z;
            o.w = Ob[i][q].w + pv.w;
            *(float4*)(orow + (chunk << 2)) = o;
        }
    }
}

// ---------------------------------------------------------------------------
extern "C" void kernel_launch(void* const* d_in, const int* in_sizes, int n_in,
                              void* d_out, int out_size)
{
    const float* f1 = (const float*)d_in[0];
    const float* f2 = (const float*)d_in[1];
    const float* f3 = (const float*)d_in[2];
    const float* w1 = (const float*)d_in[3];
    const float* b1 = (const float*)d_in[4];
    const float* w2 = (const float*)d_in[5];
    const float* b2 = (const float*)d_in[6];
    const float* w3 = (const float*)d_in[7];
    const float* b3 = (const float*)d_in[8];
    const float* a1 = (const float*)d_in[9];
    const float* a2 = (const float*)d_in[10];
    const float* a3 = (const float*)d_in[11];
    float* out = (float*)d_out;

    float *p1, *x2, *x3, *att2, *att3;
    cudaGetSymbolAddress((void**)&p1,   g_p1);
    cudaGetSymbolAddress((void**)&x2,   g_x2);
    cudaGetSymbolAddress((void**)&x3,   g_x3);
    cudaGetSymbolAddress((void**)&att2, g_att2);
    cudaGetSymbolAddress((void**)&att3, g_att3);

    // 1x1 conv projections
    proj_kernel<<<dim3((BATCH * N1D) / 64, 4), 256>>>(f1, w1, b1, p1, 256);
    proj_kernel<<<dim3((BATCH * 256) / 64, 4), 256>>>(f2, w2, b2, x2, 512);
    proj_kernel<<<dim3((BATCH * 64)  / 64, 4), 256>>>(f3, w3, b3, x3, 1024);

    // small Gram matrices
    attnt_kernel<<<dim3(4, 4, BATCH), 256>>>(x2, att2, 256);
    attnt_kernel<<<dim3(1, 1, BATCH), 256>>>(x3, att3, 64);

    // fused sigmoid-attention + output
    const int smem_bytes = (64 * 256 * 2 + 64 * 65 + 17 * 256 + 5 * 64) * 4;
    cudaFuncSetAttribute(fused_kernel,
                         cudaFuncAttributeMaxDynamicSharedMemorySize, smem_bytes);
    fused_kernel<<<dim3(16, BATCH), 256, smem_bytes>>>(p1, att2, att3,
                                                       a1, a2, a3, out);
}

// round 2
// speedup vs baseline: 1.0035x; 1.0035x over previous
#include <cuda_runtime.h>
#include <math.h>

#define BATCH 16
#define N1D 1024
#define CCH 256

// Scratch (device globals; no allocation allowed)
__device__ float g_p1[BATCH * N1D * CCH];      // 16.8 MB
__device__ float g_x2[BATCH * 256 * CCH];      // 4.2 MB
__device__ float g_x3[BATCH * 64 * CCH];       // 1.05 MB
__device__ float g_att2[BATCH * 256 * 256];    // 4.2 MB
__device__ float g_att3[BATCH * 64 * 64];      // 0.26 MB

// swizzle: chunk index XOR low-4 row bits (chunk granularity = float4)
#define SWZ(row, ck) ((((ck) ^ ((row) & 15)) << 2))

// ---------------------------------------------------------------------------
// init rows of out to bias (for K-split atomic projections)
// ---------------------------------------------------------------------------
__global__ void init_bias_kernel(float* __restrict__ out,
                                 const float* __restrict__ bias)
{
    int idx = blockIdx.x * 256 + threadIdx.x;    // float4 index
    int cj = idx & 63;                           // 64 chunks per 256-col row
    float4 bv = *(const float4*)&bias[cj * 4];
    *(float4*)&out[idx * 4] = bv;
}

// ---------------------------------------------------------------------------
// Projection: out[M,256] = A[M,KDIM] @ W[KDIM,256] (+ bias)
// 64 rows x 256 cols per CTA, per-thread 4 rows x 16 cols, kb = 32.
// gridDim.y = K-split; if >1 -> atomicAdd onto bias-preinitialized out.
// ---------------------------------------------------------------------------
__global__ __launch_bounds__(256) void proj_kernel(
    const float* __restrict__ A, const float* __restrict__ W,
    const float* __restrict__ bias, float* __restrict__ out, int KDIM)
{
    __shared__ float As[32 * 68];    // [k][row] transposed, stride 68
    __shared__ float Ws[32 * 256];   // [k][n]
    const int t  = threadIdx.x;
    const int ty = t >> 4, tx = t & 15;
    const int r0 = ty * 4;
    const int row0 = blockIdx.x * 64;
    const int kd    = KDIM / gridDim.y;
    const int kbase = blockIdx.y * kd;

    float4 acc[4][4];
#pragma unroll
    for (int i = 0; i < 4; i++)
#pragma unroll
        for (int q = 0; q < 4; q++) acc[i][q] = make_float4(0.f, 0.f, 0.f, 0.f);

    for (int k0 = 0; k0 < kd; k0 += 32) {
        const int kb = kbase + k0;
        // stage A tile 64x32 (transposed into As)
#pragma unroll
        for (int s = 0; s < 2; s++) {
            int lin = t + 256 * s;                 // 512 float4
            int row = lin >> 3, kc = lin & 7;
            float4 v = *(const float4*)&A[(size_t)(row0 + row) * KDIM + kb + kc * 4];
            As[(kc * 4 + 0) * 68 + row] = v.x;
            As[(kc * 4 + 1) * 68 + row] = v.y;
            As[(kc * 4 + 2) * 68 + row] = v.z;
            As[(kc * 4 + 3) * 68 + row] = v.w;
        }
        // stage W tile 32x256
#pragma unroll
        for (int s = 0; s < 8; s++) {
            int lin = t + 256 * s;                 // 2048 float4
            int k = lin >> 6, ck = lin & 63;
            float4 v = *(const float4*)&W[(size_t)(kb + k) * CCH + ck * 4];
            *(float4*)&Ws[k * 256 + ck * 4] = v;
        }
        __syncthreads();
#pragma unroll
        for (int k = 0; k < 32; k++) {
            float4 a4 = *(const float4*)&As[k * 68 + r0];
#pragma unroll
            for (int q = 0; q < 4; q++) {
                float4 w4 = *(const float4*)&Ws[k * 256 + (tx + 16 * q) * 4];
                acc[0][q].x += a4.x * w4.x; acc[0][q].y += a4.x * w4.y;
                acc[0][q].z += a4.x * w4.z; acc[0][q].w += a4.x * w4.w;
                acc[1][q].x += a4.y * w4.x; acc[1][q].y += a4.y * w4.y;
                acc[1][q].z += a4.y * w4.z; acc[1][q].w += a4.y * w4.w;
                acc[2][q].x += a4.z * w4.x; acc[2][q].y += a4.z * w4.y;
                acc[2][q].z += a4.z * w4.z; acc[2][q].w += a4.z * w4.w;
                acc[3][q].x += a4.w * w4.x; acc[3][q].y += a4.w * w4.y;
                acc[3][q].z += a4.w * w4.z; acc[3][q].w += a4.w * w4.w;
            }
        }
        __syncthreads();
    }

    if (gridDim.y == 1) {
#pragma unroll
        for (int q = 0; q < 4; q++) {
            float4 bv = *(const float4*)&bias[(tx + 16 * q) * 4];
#pragma unroll
            for (int i = 0; i < 4; i++) {
                float4 o;
                o.x = acc[i][q].x + bv.x; o.y = acc[i][q].y + bv.y;
                o.z = acc[i][q].z + bv.z; o.w = acc[i][q].w + bv.w;
                *(float4*)&out[(size_t)(row0 + r0 + i) * CCH + (tx + 16 * q) * 4] = o;
            }
        }
    } else {
#pragma unroll
        for (int q = 0; q < 4; q++)
#pragma unroll
            for (int i = 0; i < 4; i++) {
                float* dst = &out[(size_t)(row0 + r0 + i) * CCH + (tx + 16 * q) * 4];
                atomicAdd(dst + 0, acc[i][q].x);
                atomicAdd(dst + 1, acc[i][q].y);
                atomicAdd(dst + 2, acc[i][q].z);
                atomicAdd(dst + 3, acc[i][q].w);
            }
    }
}

// ---------------------------------------------------------------------------
// Gram 128x128 tile (att2): out[b] = X[b] @ X[b]^T, X:[N,256]
// per-thread 8x8 via 2x2 quadrant blocking, kb=16
// ---------------------------------------------------------------------------
__global__ __launch_bounds__(256) void gram128_kernel(
    const float* __restrict__ X, float* __restrict__ out, int N)
{
    __shared__ float At[16 * 132];
    __shared__ float Bt[16 * 132];
    const int b  = blockIdx.z;
    const int i0 = blockIdx.x * 128, j0 = blockIdx.y * 128;
    const int t  = threadIdx.x;
    const int ty = t >> 4, tx = t & 15;
    const int ra = ty * 4, ca = tx * 4;
    const float* Xb = X + (size_t)b * N * CCH;

    float acc[8][8];
#pragma unroll
    for (int i = 0; i < 8; i++)
#pragma unroll
        for (int j = 0; j < 8; j++) acc[i][j] = 0.f;

    for (int k0 = 0; k0 < CCH; k0 += 16) {
#pragma unroll
        for (int s = 0; s < 2; s++) {
            int lin = t + 256 * s;                 // 512
            int row = lin >> 2, kc = lin & 3;
            float4 va = *(const float4*)&Xb[(size_t)(i0 + row) * CCH + k0 + kc * 4];
            At[(kc * 4 + 0) * 132 + row] = va.x;
            At[(kc * 4 + 1) * 132 + row] = va.y;
            At[(kc * 4 + 2) * 132 + row] = va.z;
            At[(kc * 4 + 3) * 132 + row] = va.w;
            float4 vb = *(const float4*)&Xb[(size_t)(j0 + row) * CCH + k0 + kc * 4];
            Bt[(kc * 4 + 0) * 132 + row] = vb.x;
            Bt[(kc * 4 + 1) * 132 + row] = vb.y;
            Bt[(kc * 4 + 2) * 132 + row] = vb.z;
            Bt[(kc * 4 + 3) * 132 + row] = vb.w;
        }
        __syncthreads();
#pragma unroll
        for (int k = 0; k < 16; k++) {
            float4 a0 = *(const float4*)&At[k * 132 + ra];
            float4 a1 = *(const float4*)&At[k * 132 + 64 + ra];
            float4 b0 = *(const float4*)&Bt[k * 132 + ca];
            float4 b1 = *(const float4*)&Bt[k * 132 + 64 + ca];
            float av[8] = {a0.x, a0.y, a0.z, a0.w, a1.x, a1.y, a1.z, a1.w};
            float bv[8] = {b0.x, b0.y, b0.z, b0.w, b1.x, b1.y, b1.z, b1.w};
#pragma unroll
            for (int i = 0; i < 8; i++)
#pragma unroll
                for (int j = 0; j < 8; j++)
                    acc[i][j] += av[i] * bv[j];
        }
        __syncthreads();
    }

#pragma unroll
    for (int hr = 0; hr < 2; hr++)
#pragma unroll
        for (int i = 0; i < 4; i++) {
            int row = i0 + hr * 64 + ra + i;
            float4 o0, o1;
            o0.x = acc[hr*4+i][0]; o0.y = acc[hr*4+i][1];
            o0.z = acc[hr*4+i][2]; o0.w = acc[hr*4+i][3];
            o1.x = acc[hr*4+i][4]; o1.y = acc[hr*4+i][5];
            o1.z = acc[hr*4+i][6]; o1.w = acc[hr*4+i][7];
            *(float4*)&out[(size_t)b * N * N + (size_t)row * N + j0 + ca]      = o0;
            *(float4*)&out[(size_t)b * N * N + (size_t)row * N + j0 + 64 + ca] = o1;
        }
}

// ---------------------------------------------------------------------------
// Gram 64x64 (att3 only)
// ---------------------------------------------------------------------------
__global__ __launch_bounds__(256) void attnt_kernel(
    const float* __restrict__ X, float* __restrict__ out, int N)
{
    __shared__ float Ai[32][65];
    __shared__ float Bj[32][65];
    const int b  = blockIdx.z;
    const int i0 = blockIdx.x * 64, j0 = blockIdx.y * 64;
    const int t  = threadIdx.x;
    const int ty = t >> 4, tx = t & 15;
    const int r0 = ty * 4, c0 = tx * 4;
    const float* Xb = X + (size_t)b * N * CCH;

    float acc[4][4] = {};

    for (int k0 = 0; k0 < CCH; k0 += 32) {
#pragma unroll
        for (int i = 0; i < 8; i++) {
            int lin = t + 256 * i;
            int r = lin >> 5, k = lin & 31;
            Ai[k][r] = Xb[(size_t)(i0 + r) * CCH + k0 + k];
            Bj[k][r] = Xb[(size_t)(j0 + r) * CCH + k0 + k];
        }
        __syncthreads();
#pragma unroll
        for (int k = 0; k < 32; k++) {
            float a[4], bb[4];
#pragma unroll
            for (int i = 0; i < 4; i++) a[i]  = Ai[k][r0 + i];
#pragma unroll
            for (int j = 0; j < 4; j++) bb[j] = Bj[k][c0 + j];
#pragma unroll
            for (int i = 0; i < 4; i++)
#pragma unroll
                for (int j = 0; j < 4; j++)
                    acc[i][j] += a[i] * bb[j];
        }
        __syncthreads();
    }

#pragma unroll
    for (int i = 0; i < 4; i++) {
        float4 o;
        o.x = acc[i][0]; o.y = acc[i][1]; o.z = acc[i][2]; o.w = acc[i][3];
        *(float4*)&out[(size_t)b * N * N + (size_t)(i0 + r0 + i) * N + j0 + c0] = o;
    }
}

// ---------------------------------------------------------------------------
// Fused sigmoid-attention. n-tile 64, m-tile 128 (channel-halved K staging).
// GEMM1 per-thread 4x8; GEMM2 per-thread 4 rows x 2 chunks per half.
// ---------------------------------------------------------------------------
__global__ __launch_bounds__(256, 1) void fused_kernel(
    const float* __restrict__ p1,
    const float* __restrict__ att2, const float* __restrict__ att3,
    const float* __restrict__ pa1, const float* __restrict__ pa2,
    const float* __restrict__ pa3, float* __restrict__ out)
{
    extern __shared__ float sm[];
    float* Qs = sm;                  // 64 x 256 (swizzled), holds p1 n-rows
    float* Ks = Qs + 64 * 256;       // 128 x 128 (swizzled), one ch-half
    float* Ss = Ks + 128 * 128;      // 64 x 132
    float* A2 = Ss + 64 * 132;       // 17 x 256
    float* A3 = A2 + 17 * 256;       // 5 x 64

    const int b  = blockIdx.y;
    const int n0 = blockIdx.x * 64;
    const int t  = threadIdx.x;
    const int ty = t >> 4, tx = t & 15;
    const int r0 = ty * 4;

    const float* p1b = p1 + (size_t)b * N1D * CCH;
    const float sa1 = *pa1, sa2 = *pa2, sa3 = *pa3;
    const int r2lo = n0 >> 2;
    const int r3lo = n0 >> 4;

    // ---- stage Q tile (64 x 256), swizzled ----
#pragma unroll
    for (int i = 0; i < 16; i++) {
        int lin = t + 256 * i;              // 4096 float4 chunks
        int row = lin >> 6, ck = lin & 63;
        float4 v = *(const float4*)(p1b + (size_t)(n0 + row) * CCH + ck * 4);
        *(float4*)(Qs + row * 256 + SWZ(row, ck)) = v;
    }
    // ---- stage att2 window 17x256 ----
    for (int lin = t; lin < 17 * 256; lin += 256) {
        int rr = lin >> 8, cc = lin & 255;
        int src_r = min(r2lo + rr, 255);
        A2[rr * 256 + cc] = att2[((size_t)b * 256 + src_r) * 256 + cc];
    }
    // ---- stage att3 window 5x64 ----
    for (int lin = t; lin < 5 * 64; lin += 256) {
        int rr = lin >> 6, cc = lin & 63;
        int src_r = min(r3lo + rr, 63);
        A3[rr * 64 + cc] = att3[((size_t)b * 64 + src_r) * 64 + cc];
    }

    float4 Ob[4][4];
#pragma unroll
    for (int i = 0; i < 4; i++)
#pragma unroll
        for (int q = 0; q < 4; q++) Ob[i][q] = make_float4(0.f, 0.f, 0.f, 0.f);

    for (int mt = 0; mt < 8; mt++) {
        const int m0 = mt * 128;
        float acc[4][8];
#pragma unroll
        for (int i = 0; i < 4; i++)
#pragma unroll
            for (int j = 0; j < 8; j++) acc[i][j] = 0.f;

#pragma unroll 1
        for (int h = 0; h < 2; h++) {
            __syncthreads();   // prior readers of Ks done (also covers Q/A2 staging)
            // stage K half: 128 rows x 128 ch
#pragma unroll
            for (int s = 0; s < 16; s++) {
                int lin = t + 256 * s;          // 4096 float4
                int row = lin >> 5, ck = lin & 31;
                float4 v = *(const float4*)(p1b + (size_t)(m0 + row) * CCH + h * 128 + ck * 4);
                *(float4*)(Ks + row * 128 + SWZ(row, ck)) = v;
            }
            __syncthreads();
            // GEMM1 partial: S += Q(:,half) . K(:,half)^T
            const int cko = h * 32;
#pragma unroll 2
            for (int ck = 0; ck < 32; ck++) {
                float4 qv[4];
#pragma unroll
                for (int i = 0; i < 4; i++)
                    qv[i] = *(const float4*)(Qs + (r0 + i) * 256 + SWZ(r0 + i, ck + cko));
                float4 kv[8];
#pragma unroll
                for (int j = 0; j < 8; j++) {
                    int mm = tx + 16 * j;
                    kv[j] = *(const float4*)(Ks + mm * 128 + SWZ(mm, ck));
                }
#pragma unroll
                for (int i = 0; i < 4; i++)
#pragma unroll
                    for (int j = 0; j < 8; j++)
                        acc[i][j] += qv[i].x * kv[j].x + qv[i].y * kv[j].y +
                                     qv[i].z * kv[j].z + qv[i].w * kv[j].w;
            }
        }

        // ---- epilogue: gating + sigmoid -> Ss ----
#pragma unroll
        for (int i = 0; i < 4; i++) {
            const int n    = n0 + r0 + i;
            const int rn   = n >> 2;
            const float fn = (float)(n & 3) * 0.25f;
            const int i20  = rn - r2lo;
            const int i21  = min(rn + 1, 255) - r2lo;
            const int rn3  = n >> 4;
            const float fn3 = (float)(n & 15) * 0.0625f;
            const int i30  = rn3 - r3lo;
            const int i31  = min(rn3 + 1, 63) - r3lo;
            const float* Ar0 = A2 + i20 * 256;
            const float* Ar1 = A2 + i21 * 256;
            const float* Br0 = A3 + i30 * 64;
            const float* Br1 = A3 + i31 * 64;
#pragma unroll
            for (int j = 0; j < 8; j++) {
                const int m  = m0 + tx + 16 * j;
                const int rm = m >> 2;
                const float fm = (float)(m & 3) * 0.25f;
                const int c21 = min(rm + 1, 255);
                float v2 = (1.f - fn) * ((1.f - fm) * Ar0[rm] + fm * Ar0[c21]) +
                           fn        * ((1.f - fm) * Ar1[rm] + fm * Ar1[c21]);

                const int rm3 = m >> 4;
                const float fm3 = (float)(m & 15) * 0.0625f;
                const int c31 = min(rm3 + 1, 63);
                float v3 = (1.f - fn3) * ((1.f - fm3) * Br0[rm3] + fm3 * Br0[c31]) +
                           fn3        * ((1.f - fm3) * Br1[rm3] + fm3 * Br1[c31]);

                float val = sa1 * acc[i][j] + sa2 * v2 + sa3 * v3;
                Ss[(r0 + i) * 132 + tx + 16 * j] = 1.0f / (1.0f + __expf(-val));
            }
        }
        __syncthreads();   // Ss visible; Ks still holds half 1

        // ---- GEMM2 half 1 (Ks = ch 128..255): O chunks q=2,3 ----
#pragma unroll 2
        for (int m = 0; m < 128; m++) {
            float sv[4];
#pragma unroll
            for (int i = 0; i < 4; i++) sv[i] = Ss[(r0 + i) * 132 + m];
#pragma unroll
            for (int q = 0; q < 2; q++) {
                int cl = tx + 16 * q;
                float4 kv = *(const float4*)(Ks + m * 128 + SWZ(m, cl));
#pragma unroll
                for (int i = 0; i < 4; i++) {
                    Ob[i][q + 2].x += sv[i] * kv.x;
                    Ob[i][q + 2].y += sv[i] * kv.y;
                    Ob[i][q + 2].z += sv[i] * kv.z;
                    Ob[i][q + 2].w += sv[i] * kv.w;
                }
            }
        }
        __syncthreads();
        // ---- restage K half 0 ----
#pragma unroll
        for (int s = 0; s < 16; s++) {
            int lin = t + 256 * s;
            int row = lin >> 5, ck = lin & 31;
            float4 v = *(const float4*)(p1b + (size_t)(m0 + row) * CCH + ck * 4);
            *(float4*)(Ks + row * 128 + SWZ(row, ck)) = v;
        }
        __syncthreads();
        // ---- GEMM2 half 0: O chunks q=0,1 ----
#pragma unroll 2
        for (int m = 0; m < 128; m++) {
            float sv[4];
#pragma unroll
            for (int i = 0; i < 4; i++) sv[i] = Ss[(r0 + i) * 132 + m];
#pragma unroll
            for (int q = 0; q < 2; q++) {
                int cl = tx + 16 * q;
                float4 kv = *(const float4*)(Ks + m * 128 + SWZ(m, cl));
#pragma unroll
                for (int i = 0; i < 4; i++) {
                    Ob[i][q].x += sv[i] * kv.x;
                    Ob[i][q].y += sv[i] * kv.y;
                    Ob[i][q].z += sv[i] * kv.z;
                    Ob[i][q].w += sv[i] * kv.w;
                }
            }
        }
    }

    // ---- final: out = O + p1 (p1 rows resident in Qs) ----
#pragma unroll
    for (int i = 0; i < 4; i++) {
        const int n = n0 + r0 + i;
        float* orow = out + ((size_t)(b * N1D + n)) * CCH;
#pragma unroll
        for (int q = 0; q < 4; q++) {
            const int cg = tx + 16 * q;
            float4 pv = *(const float4*)(Qs + (r0 + i) * 256 + SWZ(r0 + i, cg));
            float4 o;
            o.x = Ob[i][q].x + pv.x;
            o.y = Ob[i][q].y + pv.y;
            o.z = Ob[i][q].z + pv.z;
            o.w = Ob[i][q].w + pv.w;
            *(float4*)(orow + cg * 4) = o;
        }
    }
}

// ---------------------------------------------------------------------------
extern "C" void kernel_launch(void* const* d_in, const int* in_sizes, int n_in,
                              void* d_out, int out_size)
{
    const float* f1 = (const float*)d_in[0];
    const float* f2 = (const float*)d_in[1];
    const float* f3 = (const float*)d_in[2];
    const float* w1 = (const float*)d_in[3];
    const float* b1 = (const float*)d_in[4];
    const float* w2 = (const float*)d_in[5];
    const float* b2 = (const float*)d_in[6];
    const float* w3 = (const float*)d_in[7];
    const float* b3 = (const float*)d_in[8];
    const float* a1 = (const float*)d_in[9];
    const float* a2 = (const float*)d_in[10];
    const float* a3 = (const float*)d_in[11];
    float* out = (float*)d_out;

    float *p1, *x2, *x3, *att2, *att3;
    cudaGetSymbolAddress((void**)&p1,   g_p1);
    cudaGetSymbolAddress((void**)&x2,   g_x2);
    cudaGetSymbolAddress((void**)&x3,   g_x3);
    cudaGetSymbolAddress((void**)&att2, g_att2);
    cudaGetSymbolAddress((void**)&att3, g_att3);

    // bias pre-init for K-split projections
    init_bias_kernel<<<(BATCH * 256 * CCH) / 1024, 256>>>(x2, b2);
    init_bias_kernel<<<(BATCH * 64  * CCH) / 1024, 256>>>(x3, b3);

    // 1x1 conv projections
    proj_kernel<<<dim3((BATCH * N1D) / 64, 1), 256>>>(f1, w1, b1, p1, 256);
    proj_kernel<<<dim3((BATCH * 256) / 64, 2), 256>>>(f2, w2, b2, x2, 512);
    proj_kernel<<<dim3((BATCH * 64)  / 64, 4), 256>>>(f3, w3, b3, x3, 1024);

    // small Gram matrices
    gram128_kernel<<<dim3(2, 2, BATCH), 256>>>(x2, att2, 256);
    attnt_kernel<<<dim3(1, 1, BATCH), 256>>>(x3, att3, 64);

    // fused sigmoid-attention + output
    const int smem_bytes = (64 * 256 + 128 * 128 + 64 * 132 + 17 * 256 + 5 * 64) * 4;
    cudaFuncSetAttribute(fused_kernel,
                         cudaFuncAttributeMaxDynamicSharedMemorySize, smem_bytes);
    fused_kernel<<<dim3(16, BATCH), 256, smem_bytes>>>(p1, att2, att3,
                                                       a1, a2, a3, out);
}